// round 8
// baseline (speedup 1.0000x reference)
#include <cuda_runtime.h>
#include <cstdint>

// Problem constants (fixed by the reference: N=8192, D=512, OUT=1)
#define NROWS 8192
#define DDIM  512
#define BK    32
#define SPAD  132   // 128 + 4: keeps float4 smem reads 16B-aligned, limits store conflicts

// Scratch (no allocations allowed in kernel_launch — __device__ globals instead)
__device__ float g_y[(size_t)NROWS * DDIM];  // y = x * rho  (16 MB)
__device__ float g_d[NROWS];                 // softplus variances for the diagonal

// ---------------------------------------------------------------------------
// Kernel 1: one warp per row. Computes mu[i], d[i], and y[i][:] = x[i][:]*rho.
// ---------------------------------------------------------------------------
__global__ void prep_kernel(const float* __restrict__ x,
                            const float* __restrict__ mu_k,
                            const float* __restrict__ rho,
                            const float* __restrict__ var_k,
                            const float* __restrict__ mu_b,
                            const float* __restrict__ var_b,
                            float* __restrict__ mu_out) {
    int warp = (int)((blockIdx.x * blockDim.x + threadIdx.x) >> 5);
    int lane = threadIdx.x & 31;
    if (warp >= NROWS) return;

    const float* xr = x + (size_t)warp * DDIM;
    float*       yr = g_y + (size_t)warp * DDIM;

    float smu = 0.f, sv = 0.f;
#pragma unroll
    for (int k = lane; k < DDIM; k += 32) {
        float xv = xr[k];
        smu = fmaf(xv, mu_k[k], smu);
        sv  = fmaf(xv, var_k[k], sv);
        yr[k] = xv * rho[k];
    }
#pragma unroll
    for (int o = 16; o > 0; o >>= 1) {
        smu += __shfl_down_sync(0xffffffffu, smu, o);
        sv  += __shfl_down_sync(0xffffffffu, sv,  o);
    }
    if (lane == 0) {
        mu_out[warp] = smu + mu_b[0];
        float z  = sv + var_b[0];
        float sp = (z > 20.f) ? z : log1pf(expf(z));  // stable softplus
        g_d[warp] = sp + 1e-8f;
    }
}

// ---------------------------------------------------------------------------
// Kernel 2: symmetric SGEMM  C = y @ x^T + cov_bias  (both operands K-major).
// 128x128 block tile, BK=32, 256 threads, 8x8 micro-tile per thread.
// Only upper-triangular block grid computes; mirror tile written transposed.
// Inner product uses packed fma.rn.f32x2 (2 fp32 FMAs / instr, bit-exact fp32).
// ---------------------------------------------------------------------------
union F4U { float4 f; float s[4]; unsigned long long u[2]; };

__global__ __launch_bounds__(256, 2)
void cov_gemm(const float* __restrict__ X,
              float* __restrict__ C,
              const float* __restrict__ cov_b) {
    const int bi = blockIdx.y;   // row-tile
    const int bj = blockIdx.x;   // col-tile
    if (bj < bi) return;         // symmetry: compute upper triangle only

    __shared__ float sa[BK][SPAD];  // A tile, transposed: sa[k][i]
    __shared__ float sb[BK][SPAD];  // B tile, transposed: sb[k][j]

    const int tid = threadIdx.x;
    const int tx  = tid & 15;       // column group
    const int ty  = tid >> 4;       // row group
    const int i0  = bi << 7;
    const int j0  = bj << 7;

    const int lrow = tid >> 3;        // 0..31   (tile row for loads)
    const int lk   = (tid & 7) << 2;  // 0..28   (k offset, float4)

    const float* Ap = g_y + (size_t)(i0 + lrow) * DDIM + lk;
    const float* Bp = X   + (size_t)(j0 + lrow) * DDIM + lk;

    unsigned long long acc[8][4];     // 8 rows x 4 packed-f32x2 column pairs
#pragma unroll
    for (int i = 0; i < 8; i++)
#pragma unroll
        for (int jp = 0; jp < 4; jp++) acc[i][jp] = 0ull;

    for (int k0 = 0; k0 < DDIM; k0 += BK) {
        // ---- load 128x32 tiles (coalesced float4), transpose into smem ----
#pragma unroll
        for (int it = 0; it < 4; it++) {
            float4 a = *(const float4*)(Ap + k0 + (size_t)(it * 32) * DDIM);
            float4 b = *(const float4*)(Bp + k0 + (size_t)(it * 32) * DDIM);
            int r = lrow + it * 32;
            sa[lk + 0][r] = a.x; sa[lk + 1][r] = a.y; sa[lk + 2][r] = a.z; sa[lk + 3][r] = a.w;
            sb[lk + 0][r] = b.x; sb[lk + 1][r] = b.y; sb[lk + 2][r] = b.z; sb[lk + 3][r] = b.w;
        }
        __syncthreads();

        // ---- compute ----
#pragma unroll
        for (int k = 0; k < BK; k++) {
            F4U a0, a1, b0, b1;
            a0.f = *(const float4*)&sa[k][ty * 8];
            a1.f = *(const float4*)&sa[k][ty * 8 + 4];
            b0.f = *(const float4*)&sb[k][tx * 8];
            b1.f = *(const float4*)&sb[k][tx * 8 + 4];

            unsigned long long bp[4] = { b0.u[0], b0.u[1], b1.u[0], b1.u[1] };
            float av[8] = { a0.s[0], a0.s[1], a0.s[2], a0.s[3],
                            a1.s[0], a1.s[1], a1.s[2], a1.s[3] };
#pragma unroll
            for (int i = 0; i < 8; i++) {
                unsigned long long ap;
                unsigned int ar = __float_as_uint(av[i]);
                asm("mov.b64 %0, {%1, %1};" : "=l"(ap) : "r"(ar));
#pragma unroll
                for (int jp = 0; jp < 4; jp++) {
                    asm("fma.rn.f32x2 %0, %1, %2, %0;"
                        : "+l"(acc[i][jp]) : "l"(ap), "l"(bp[jp]));
                }
            }
        }
        __syncthreads();
    }

    // ---- epilogue: unpack, add bias ----
    const float cb = cov_b[0];
    float c[8][8];
#pragma unroll
    for (int i = 0; i < 8; i++)
#pragma unroll
        for (int jp = 0; jp < 4; jp++) {
            unsigned int lo, hi;
            asm("mov.b64 {%0, %1}, %2;" : "=r"(lo), "=r"(hi) : "l"(acc[i][jp]));
            c[i][2 * jp]     = __uint_as_float(lo) + cb;
            c[i][2 * jp + 1] = __uint_as_float(hi) + cb;
        }

    // normal tile
#pragma unroll
    for (int i = 0; i < 8; i++) {
        size_t off = (size_t)(i0 + ty * 8 + i) * NROWS + (size_t)(j0 + tx * 8);
        *(float4*)(C + off)     = make_float4(c[i][0], c[i][1], c[i][2], c[i][3]);
        *(float4*)(C + off + 4) = make_float4(c[i][4], c[i][5], c[i][6], c[i][7]);
    }
    // mirror tile (transposed) for the lower triangle
    if (bj != bi) {
#pragma unroll
        for (int v = 0; v < 8; v++) {
            size_t off = (size_t)(j0 + tx * 8 + v) * NROWS + (size_t)(i0 + ty * 8);
            *(float4*)(C + off)     = make_float4(c[0][v], c[1][v], c[2][v], c[3][v]);
            *(float4*)(C + off + 4) = make_float4(c[4][v], c[5][v], c[6][v], c[7][v]);
        }
    }
}

// ---------------------------------------------------------------------------
// Kernel 3: overwrite the diagonal with the softplus variances.
// ---------------------------------------------------------------------------
__global__ void set_diag(float* __restrict__ C) {
    int i = blockIdx.x * blockDim.x + threadIdx.x;
    if (i < NROWS) C[(size_t)i * NROWS + i] = g_d[i];
}

// ---------------------------------------------------------------------------
// Launch. Output layout: out[0:8192] = mu (8192x1), out[8192:] = cov (8192x8192).
// ---------------------------------------------------------------------------
extern "C" void kernel_launch(void* const* d_in, const int* in_sizes, int n_in,
                              void* d_out, int out_size) {
    (void)in_sizes; (void)n_in; (void)out_size;
    const float* x     = (const float*)d_in[0];
    const float* mu_k  = (const float*)d_in[1];
    const float* rho   = (const float*)d_in[2];
    const float* var_k = (const float*)d_in[3];
    const float* mu_b  = (const float*)d_in[4];
    const float* var_b = (const float*)d_in[5];
    const float* cov_b = (const float*)d_in[6];

    float* out = (float*)d_out;
    float* mu  = out;
    float* cov = out + NROWS;

    // 8192 warps -> 1024 blocks of 256 threads
    prep_kernel<<<NROWS / 8, 256>>>(x, mu_k, rho, var_k, mu_b, var_b, mu);

    dim3 grid(NROWS / 128, NROWS / 128);  // 64 x 64 tiles; lower triangle exits early
    cov_gemm<<<grid, 256>>>(x, cov, cov_b);

    set_diag<<<NROWS / 256, 256>>>(cov);
}

// round 9
// speedup vs baseline: 1.0004x; 1.0004x over previous
#include <cuda_runtime.h>
#include <cstdint>

// Problem constants (fixed by the reference: N=8192, D=512, OUT=1)
#define NROWS 8192
#define DDIM  512
#define BK    32
#define SPAD  132   // 128 + 4: keeps float4 smem reads 16B-aligned, limits store conflicts

// Scratch (no allocations allowed in kernel_launch — __device__ globals instead)
__device__ float g_y[(size_t)NROWS * DDIM];  // y = x * rho  (16 MB)
__device__ float g_d[NROWS];                 // softplus variances for the diagonal

// ---------------------------------------------------------------------------
// Kernel 1: one warp per row. Computes mu[i], d[i], and y[i][:] = x[i][:]*rho.
// ---------------------------------------------------------------------------
__global__ void prep_kernel(const float* __restrict__ x,
                            const float* __restrict__ mu_k,
                            const float* __restrict__ rho,
                            const float* __restrict__ var_k,
                            const float* __restrict__ mu_b,
                            const float* __restrict__ var_b,
                            float* __restrict__ mu_out) {
    int warp = (int)((blockIdx.x * blockDim.x + threadIdx.x) >> 5);
    int lane = threadIdx.x & 31;
    if (warp >= NROWS) return;

    const float* xr = x + (size_t)warp * DDIM;
    float*       yr = g_y + (size_t)warp * DDIM;

    float smu = 0.f, sv = 0.f;
#pragma unroll
    for (int k = lane; k < DDIM; k += 32) {
        float xv = xr[k];
        smu = fmaf(xv, mu_k[k], smu);
        sv  = fmaf(xv, var_k[k], sv);
        yr[k] = xv * rho[k];
    }
#pragma unroll
    for (int o = 16; o > 0; o >>= 1) {
        smu += __shfl_down_sync(0xffffffffu, smu, o);
        sv  += __shfl_down_sync(0xffffffffu, sv,  o);
    }
    if (lane == 0) {
        mu_out[warp] = smu + mu_b[0];
        float z  = sv + var_b[0];
        float sp = (z > 20.f) ? z : log1pf(expf(z));  // stable softplus
        g_d[warp] = sp + 1e-8f;
    }
}

// ---------------------------------------------------------------------------
// Kernel 2: symmetric SGEMM  C = y @ x^T + cov_bias  (both operands K-major).
// 128x128 block tile, BK=32, 256 threads, 8x8 micro-tile per thread.
// Only upper-triangular block grid computes; mirror tile written transposed.
// Inner product uses packed fma.rn.f32x2 (2 fp32 FMAs / instr, bit-exact fp32).
// ---------------------------------------------------------------------------
union F4U { float4 f; float s[4]; unsigned long long u[2]; };

__global__ __launch_bounds__(256, 2)
void cov_gemm(const float* __restrict__ X,
              float* __restrict__ C,
              const float* __restrict__ cov_b) {
    const int bi = blockIdx.y;   // row-tile
    const int bj = blockIdx.x;   // col-tile
    if (bj < bi) return;         // symmetry: compute upper triangle only

    __shared__ float sa[BK][SPAD];  // A tile, transposed: sa[k][i]
    __shared__ float sb[BK][SPAD];  // B tile, transposed: sb[k][j]

    const int tid = threadIdx.x;
    const int tx  = tid & 15;       // column group
    const int ty  = tid >> 4;       // row group
    const int i0  = bi << 7;
    const int j0  = bj << 7;

    const int lrow = tid >> 3;        // 0..31   (tile row for loads)
    const int lk   = (tid & 7) << 2;  // 0..28   (k offset, float4)

    const float* Ap = g_y + (size_t)(i0 + lrow) * DDIM + lk;
    const float* Bp = X   + (size_t)(j0 + lrow) * DDIM + lk;

    unsigned long long acc[8][4];     // 8 rows x 4 packed-f32x2 column pairs
#pragma unroll
    for (int i = 0; i < 8; i++)
#pragma unroll
        for (int jp = 0; jp < 4; jp++) acc[i][jp] = 0ull;

    for (int k0 = 0; k0 < DDIM; k0 += BK) {
        // ---- load 128x32 tiles (coalesced float4), transpose into smem ----
#pragma unroll
        for (int it = 0; it < 4; it++) {
            float4 a = *(const float4*)(Ap + k0 + (size_t)(it * 32) * DDIM);
            float4 b = *(const float4*)(Bp + k0 + (size_t)(it * 32) * DDIM);
            int r = lrow + it * 32;
            sa[lk + 0][r] = a.x; sa[lk + 1][r] = a.y; sa[lk + 2][r] = a.z; sa[lk + 3][r] = a.w;
            sb[lk + 0][r] = b.x; sb[lk + 1][r] = b.y; sb[lk + 2][r] = b.z; sb[lk + 3][r] = b.w;
        }
        __syncthreads();

        // ---- compute ----
#pragma unroll
        for (int k = 0; k < BK; k++) {
            F4U a0, a1, b0, b1;
            a0.f = *(const float4*)&sa[k][ty * 8];
            a1.f = *(const float4*)&sa[k][ty * 8 + 4];
            b0.f = *(const float4*)&sb[k][tx * 8];
            b1.f = *(const float4*)&sb[k][tx * 8 + 4];

            unsigned long long bp[4] = { b0.u[0], b0.u[1], b1.u[0], b1.u[1] };
            float av[8] = { a0.s[0], a0.s[1], a0.s[2], a0.s[3],
                            a1.s[0], a1.s[1], a1.s[2], a1.s[3] };
#pragma unroll
            for (int i = 0; i < 8; i++) {
                unsigned long long ap;
                unsigned int ar = __float_as_uint(av[i]);
                asm("mov.b64 %0, {%1, %1};" : "=l"(ap) : "r"(ar));
#pragma unroll
                for (int jp = 0; jp < 4; jp++) {
                    asm("fma.rn.f32x2 %0, %1, %2, %0;"
                        : "+l"(acc[i][jp]) : "l"(ap), "l"(bp[jp]));
                }
            }
        }
        __syncthreads();
    }

    // ---- epilogue: unpack, add bias ----
    const float cb = cov_b[0];
    float c[8][8];
#pragma unroll
    for (int i = 0; i < 8; i++)
#pragma unroll
        for (int jp = 0; jp < 4; jp++) {
            unsigned int lo, hi;
            asm("mov.b64 {%0, %1}, %2;" : "=r"(lo), "=r"(hi) : "l"(acc[i][jp]));
            c[i][2 * jp]     = __uint_as_float(lo) + cb;
            c[i][2 * jp + 1] = __uint_as_float(hi) + cb;
        }

    // normal tile
#pragma unroll
    for (int i = 0; i < 8; i++) {
        size_t off = (size_t)(i0 + ty * 8 + i) * NROWS + (size_t)(j0 + tx * 8);
        *(float4*)(C + off)     = make_float4(c[i][0], c[i][1], c[i][2], c[i][3]);
        *(float4*)(C + off + 4) = make_float4(c[i][4], c[i][5], c[i][6], c[i][7]);
    }
    // mirror tile (transposed) for the lower triangle
    if (bj != bi) {
#pragma unroll
        for (int v = 0; v < 8; v++) {
            size_t off = (size_t)(j0 + tx * 8 + v) * NROWS + (size_t)(i0 + ty * 8);
            *(float4*)(C + off)     = make_float4(c[0][v], c[1][v], c[2][v], c[3][v]);
            *(float4*)(C + off + 4) = make_float4(c[4][v], c[5][v], c[6][v], c[7][v]);
        }
    }
}

// ---------------------------------------------------------------------------
// Kernel 3: overwrite the diagonal with the softplus variances.
// ---------------------------------------------------------------------------
__global__ void set_diag(float* __restrict__ C) {
    int i = blockIdx.x * blockDim.x + threadIdx.x;
    if (i < NROWS) C[(size_t)i * NROWS + i] = g_d[i];
}

// ---------------------------------------------------------------------------
// Launch. Output layout: out[0:8192] = mu (8192x1), out[8192:] = cov (8192x8192).
// ---------------------------------------------------------------------------
extern "C" void kernel_launch(void* const* d_in, const int* in_sizes, int n_in,
                              void* d_out, int out_size) {
    (void)in_sizes; (void)n_in; (void)out_size;
    const float* x     = (const float*)d_in[0];
    const float* mu_k  = (const float*)d_in[1];
    const float* rho   = (const float*)d_in[2];
    const float* var_k = (const float*)d_in[3];
    const float* mu_b  = (const float*)d_in[4];
    const float* var_b = (const float*)d_in[5];
    const float* cov_b = (const float*)d_in[6];

    float* out = (float*)d_out;
    float* mu  = out;
    float* cov = out + NROWS;

    // 8192 warps -> 1024 blocks of 256 threads
    prep_kernel<<<NROWS / 8, 256>>>(x, mu_k, rho, var_k, mu_b, var_b, mu);

    dim3 grid(NROWS / 128, NROWS / 128);  // 64 x 64 tiles; lower triangle exits early
    cov_gemm<<<grid, 256>>>(x, cov, cov_b);

    set_diag<<<NROWS / 256, 256>>>(cov);
}

// round 11
// speedup vs baseline: 2.3725x; 2.3715x over previous
#include <cuda_runtime.h>
#include <cuda_bf16.h>
#include <cstdint>

// Problem constants: N=8192, D=512, OUT=1
#define NROWS 8192
#define DDIM  512
#define KBIG  1536            // split-bf16 concatenated K: [hi | cross | cross]
#define BK    64              // bf16 per K-chunk = 128 bytes/row
#define NCHUNK (KBIG / BK)    // 24
#define NSTAGE 4
#define STAGE_BYTES 32768     // A 128x64x2 = 16KB + B 16KB
#define SMEM_TOTAL (NSTAGE * STAGE_BYTES)   // 131072
#define TPITCH 132            // fp32 pitch for epilogue transpose buffer

// Scratch in __device__ globals (no allocations allowed)
__device__ __nv_bfloat16 g_X[(size_t)NROWS * KBIG];  // [xh | xl | xh]
__device__ __nv_bfloat16 g_Y[(size_t)NROWS * KBIG];  // [yh | yh | yl]
__device__ float g_d[NROWS];

// ---------------- helpers ----------------
__device__ __forceinline__ uint32_t smem_u32(const void* p) {
    uint32_t a;
    asm("{ .reg .u64 t; cvta.to.shared.u64 t, %1; cvt.u32.u64 %0, t; }" : "=r"(a) : "l"(p));
    return a;
}
__device__ __forceinline__ void cpa16(uint32_t s, const void* g) {
    asm volatile("cp.async.cg.shared.global [%0], [%1], 16;"
                 :: "r"(s), "l"(__cvta_generic_to_global(g)) : "memory");
}
#define SWZ(o) ((o) ^ (((o) >> 3) & 0x70))

__device__ __forceinline__ void ldsm_x4(uint32_t* r, uint32_t addr) {
    asm volatile("ldmatrix.sync.aligned.m8n8.x4.shared.b16 {%0,%1,%2,%3}, [%4];"
                 : "=r"(r[0]), "=r"(r[1]), "=r"(r[2]), "=r"(r[3]) : "r"(addr));
}
__device__ __forceinline__ void mma16816(float* c, const uint32_t* a, uint32_t b0, uint32_t b1) {
    asm volatile("mma.sync.aligned.m16n8k16.row.col.f32.bf16.bf16.f32 "
                 "{%0,%1,%2,%3}, {%4,%5,%6,%7}, {%8,%9}, {%0,%1,%2,%3};"
                 : "+f"(c[0]), "+f"(c[1]), "+f"(c[2]), "+f"(c[3])
                 : "r"(a[0]), "r"(a[1]), "r"(a[2]), "r"(a[3]), "r"(b0), "r"(b1));
}

// ---------------------------------------------------------------------------
// Kernel 1: one warp per row — mu, softplus d, split-bf16 operand build.
// ---------------------------------------------------------------------------
__global__ void prep_kernel(const float* __restrict__ x,
                            const float* __restrict__ mu_k,
                            const float* __restrict__ rho,
                            const float* __restrict__ var_k,
                            const float* __restrict__ mu_b,
                            const float* __restrict__ var_b,
                            float* __restrict__ mu_out) {
    int row  = (int)((blockIdx.x * blockDim.x + threadIdx.x) >> 5);
    int lane = threadIdx.x & 31;
    if (row >= NROWS) return;

    const float* xr = x + (size_t)row * DDIM;
    __nv_bfloat16* Xr = g_X + (size_t)row * KBIG;
    __nv_bfloat16* Yr = g_Y + (size_t)row * KBIG;

    float smu = 0.f, sv = 0.f;
#pragma unroll
    for (int k = lane; k < DDIM; k += 32) {
        float xv = xr[k];
        smu = fmaf(xv, mu_k[k], smu);
        sv  = fmaf(xv, var_k[k], sv);
        float yv = xv * rho[k];

        __nv_bfloat16 xh = __float2bfloat16(xv);
        __nv_bfloat16 xl = __float2bfloat16(xv - __bfloat162float(xh));
        __nv_bfloat16 yh = __float2bfloat16(yv);
        __nv_bfloat16 yl = __float2bfloat16(yv - __bfloat162float(yh));

        Xr[k] = xh; Xr[DDIM + k] = xl; Xr[2 * DDIM + k] = xh;
        Yr[k] = yh; Yr[DDIM + k] = yh; Yr[2 * DDIM + k] = yl;
    }
#pragma unroll
    for (int o = 16; o > 0; o >>= 1) {
        smu += __shfl_down_sync(0xffffffffu, smu, o);
        sv  += __shfl_down_sync(0xffffffffu, sv,  o);
    }
    if (lane == 0) {
        mu_out[row] = smu + mu_b[0];
        float z  = sv + var_b[0];
        float sp = (z > 20.f) ? z : log1pf(expf(z));
        g_d[row] = sp + 1e-8f;
    }
}

// ---------------------------------------------------------------------------
// Kernel 2: bf16 HMMA GEMM (mma.sync m16n8k16), tile 128x128, K=1536,
// 4-stage cp.async pipeline, triangular grid + smem-transposed mirror write.
// ---------------------------------------------------------------------------
__global__ __launch_bounds__(256, 1)
void cov_gemm_mma(float* __restrict__ C, const float* __restrict__ cov_b) {
    extern __shared__ char smem[];
    const uint32_t sb = smem_u32(smem);
    const int tid  = threadIdx.x;
    const int wid  = tid >> 5;
    const int lane = tid & 31;
    const int wm   = wid >> 1;   // 0..3  -> m offset wm*32
    const int wn   = wid & 1;    // 0..1  -> n offset wn*64

    // blockIdx -> (r, c) with r <= c  (b = c(c+1)/2 + r)
    int b = blockIdx.x;
    int c = (int)((sqrtf(8.0f * (float)b + 1.0f) - 1.0f) * 0.5f);
    while ((c + 1) * (c + 2) / 2 <= b) c++;
    while (c * (c + 1) / 2 > b) c--;
    const int r  = b - c * (c + 1) / 2;
    const int i0 = r << 7;   // rows
    const int j0 = c << 7;   // cols (j0 >= i0)

    const __nv_bfloat16* Ab = g_Y + (size_t)i0 * KBIG;
    const __nv_bfloat16* Bb = g_X + (size_t)j0 * KBIG;

    // per-thread load coords: 4 A vectors + 4 B vectors per chunk
    const int lrow = tid >> 3;        // 0..31 base row
    const int lc16 = tid & 7;         // 16B column

    float acc[2][8][4];
#pragma unroll
    for (int mt = 0; mt < 2; mt++)
#pragma unroll
        for (int nt = 0; nt < 8; nt++)
#pragma unroll
            for (int q = 0; q < 4; q++) acc[mt][nt][q] = 0.f;

    // ---- stage loader ----
    auto load_stage = [&](int s, int kt) {
        const int k0 = kt * BK;
        const uint32_t sA = sb + s * STAGE_BYTES;
        const uint32_t sB = sA + 16384;
#pragma unroll
        for (int it = 0; it < 4; it++) {
            int row = lrow + it * 32;
            uint32_t so = SWZ(row * 128 + lc16 * 16);
            cpa16(sA + so, Ab + (size_t)row * KBIG + k0 + lc16 * 8);
            cpa16(sB + so, Bb + (size_t)row * KBIG + k0 + lc16 * 8);
        }
    };

    // ---- prologue ----
#pragma unroll
    for (int s = 0; s < NSTAGE - 1; s++) {
        load_stage(s, s);
        asm volatile("cp.async.commit_group;" ::: "memory");
    }

    // ldmatrix lane addressing (constant per thread)
    const int a_row = lane & 15;          // row within 16-row m-tile
    const int a_kb  = (lane >> 4) * 16;   // 0 or 16 bytes (k half)
    const int b_g   = lane >> 3;          // 0..3
    const int b_r   = lane & 7;
    const int b_row = ((b_g >> 1) * 8) + b_r;   // row within 16-row n-quad
    const int b_kb  = (b_g & 1) * 16;

    // ---- main loop ----
    for (int kt = 0; kt < NCHUNK; kt++) {
        asm volatile("cp.async.wait_group 2;" ::: "memory");
        __syncthreads();

        if (kt + NSTAGE - 1 < NCHUNK) load_stage((kt + NSTAGE - 1) & (NSTAGE - 1), kt + NSTAGE - 1);
        asm volatile("cp.async.commit_group;" ::: "memory");

        const uint32_t sA = sb + (kt & (NSTAGE - 1)) * STAGE_BYTES;
        const uint32_t sB = sA + 16384;

#pragma unroll
        for (int kk = 0; kk < 4; kk++) {   // four k16 steps per chunk
            uint32_t afr[2][4];
#pragma unroll
            for (int mt = 0; mt < 2; mt++) {
                int row = wm * 32 + mt * 16 + a_row;
                ldsm_x4(afr[mt], sA + SWZ(row * 128 + kk * 32 + a_kb));
            }
            uint32_t bfr[4][4];
#pragma unroll
            for (int q = 0; q < 4; q++) {  // n-quads of 16
                int row = wn * 64 + q * 16 + b_row;
                ldsm_x4(bfr[q], sB + SWZ(row * 128 + kk * 32 + b_kb));
            }
#pragma unroll
            for (int mt = 0; mt < 2; mt++)
#pragma unroll
                for (int nt = 0; nt < 8; nt++) {
                    int q = nt >> 1, h = nt & 1;
                    mma16816(acc[mt][nt], afr[mt], bfr[q][2 * h], bfr[q][2 * h + 1]);
                }
        }
    }
    asm volatile("cp.async.wait_group 0;" ::: "memory");
    __syncthreads();   // pipeline done; smem now reusable for transpose

    // ---- epilogue ----
    const float cb = cov_b[0];
    const int g4 = lane >> 2;          // fragment row group 0..7
    const int t2 = lane & 3;           // fragment col pair

    float* st = (float*)smem;          // 128 x TPITCH transpose buffer

#pragma unroll
    for (int mt = 0; mt < 2; mt++)
#pragma unroll
        for (int nt = 0; nt < 8; nt++) {
            int il = wm * 32 + mt * 16 + g4;       // local row
            int jl = wn * 64 + nt * 8 + t2 * 2;    // local col
            float v0 = acc[mt][nt][0] + cb;
            float v1 = acc[mt][nt][1] + cb;
            float v2 = acc[mt][nt][2] + cb;
            float v3 = acc[mt][nt][3] + cb;

            // primary write (32B contiguous per 8-row group)
            size_t o0 = (size_t)(i0 + il) * NROWS + (j0 + jl);
            size_t o1 = (size_t)(i0 + il + 8) * NROWS + (j0 + jl);
            *(float2*)(C + o0) = make_float2(v0, v1);
            *(float2*)(C + o1) = make_float2(v2, v3);

            // transposed stash for the mirror (conflict-free scalar stores)
            st[(jl + 0) * TPITCH + il]     = v0;
            st[(jl + 1) * TPITCH + il]     = v1;
            st[(jl + 0) * TPITCH + il + 8] = v2;
            st[(jl + 1) * TPITCH + il + 8] = v3;
        }

    if (r != c) {   // strictly-upper tiles: coalesced mirror into lower triangle
        __syncthreads();
#pragma unroll
        for (int it = 0; it < 16; it++) {
            int jj = it * 8 + wid;
            float4 v = *(float4*)(st + jj * TPITCH + lane * 4);
            *(float4*)(C + (size_t)(j0 + jj) * NROWS + i0 + lane * 4) = v;
        }
    }
}

// ---------------------------------------------------------------------------
// Kernel 3: diagonal overwrite.
// ---------------------------------------------------------------------------
__global__ void set_diag(float* __restrict__ C) {
    int i = blockIdx.x * blockDim.x + threadIdx.x;
    if (i < NROWS) C[(size_t)i * NROWS + i] = g_d[i];
}

// ---------------------------------------------------------------------------
extern "C" void kernel_launch(void* const* d_in, const int* in_sizes, int n_in,
                              void* d_out, int out_size) {
    (void)in_sizes; (void)n_in; (void)out_size;
    const float* x     = (const float*)d_in[0];
    const float* mu_k  = (const float*)d_in[1];
    const float* rho   = (const float*)d_in[2];
    const float* var_k = (const float*)d_in[3];
    const float* mu_b  = (const float*)d_in[4];
    const float* var_b = (const float*)d_in[5];
    const float* cov_b = (const float*)d_in[6];

    float* out = (float*)d_out;
    float* mu  = out;
    float* cov = out + NROWS;

    cudaFuncSetAttribute(cov_gemm_mma, cudaFuncAttributeMaxDynamicSharedMemorySize, SMEM_TOTAL);

    prep_kernel<<<NROWS / 8, 256>>>(x, mu_k, rho, var_k, mu_b, var_b, mu);

    // 2080 = 64*65/2 upper-triangular 128x128 tiles (incl. diagonal)
    cov_gemm_mma<<<2080, 256, SMEM_TOTAL>>>(cov, cov_b);

    set_diag<<<NROWS / 256, 256>>>(cov);
}

// round 12
// speedup vs baseline: 2.7241x; 1.1482x over previous
#include <cuda_runtime.h>
#include <cuda_bf16.h>
#include <cstdint>

// Problem constants: N=8192, D=512, OUT=1
#define NROWS 8192
#define DDIM  512
#define KBIG  1536            // split-bf16 concatenated K: [hi | cross | cross]
#define BK    64              // bf16 per K-chunk = 128 bytes/row
#define NCHUNK (KBIG / BK)    // 24
#define NSTAGE 3
#define STAGE_BYTES 49152     // A 128x64x2 = 16KB + B 256x64x2 = 32KB
#define SMEM_TOTAL (NSTAGE * STAGE_BYTES)   // 147456
#define TPITCH 132            // fp32 pitch for epilogue transpose buffer

// Scratch in __device__ globals (no allocations allowed)
__device__ __nv_bfloat16 g_X[(size_t)NROWS * KBIG];  // [xh | xl | xh]
__device__ __nv_bfloat16 g_Y[(size_t)NROWS * KBIG];  // [yh | yh | yl]
__device__ float g_d[NROWS];

// ---------------- helpers ----------------
__device__ __forceinline__ uint32_t smem_u32(const void* p) {
    uint32_t a;
    asm("{ .reg .u64 t; cvta.to.shared.u64 t, %1; cvt.u32.u64 %0, t; }" : "=r"(a) : "l"(p));
    return a;
}
__device__ __forceinline__ void cpa16(uint32_t s, const void* g) {
    asm volatile("cp.async.cg.shared.global [%0], [%1], 16;"
                 :: "r"(s), "l"(__cvta_generic_to_global(g)) : "memory");
}
#define SWZ(o) ((o) ^ (((o) >> 3) & 0x70))

__device__ __forceinline__ void ldsm_x4(uint32_t* r, uint32_t addr) {
    asm volatile("ldmatrix.sync.aligned.m8n8.x4.shared.b16 {%0,%1,%2,%3}, [%4];"
                 : "=r"(r[0]), "=r"(r[1]), "=r"(r[2]), "=r"(r[3]) : "r"(addr));
}
__device__ __forceinline__ void mma16816(float* c, const uint32_t* a, uint32_t b0, uint32_t b1) {
    asm volatile("mma.sync.aligned.m16n8k16.row.col.f32.bf16.bf16.f32 "
                 "{%0,%1,%2,%3}, {%4,%5,%6,%7}, {%8,%9}, {%0,%1,%2,%3};"
                 : "+f"(c[0]), "+f"(c[1]), "+f"(c[2]), "+f"(c[3])
                 : "r"(a[0]), "r"(a[1]), "r"(a[2]), "r"(a[3]), "r"(b0), "r"(b1));
}

// ---------------------------------------------------------------------------
// Kernel 1: one warp per row — mu, softplus d, split-bf16 operand build.
// ---------------------------------------------------------------------------
__global__ void prep_kernel(const float* __restrict__ x,
                            const float* __restrict__ mu_k,
                            const float* __restrict__ rho,
                            const float* __restrict__ var_k,
                            const float* __restrict__ mu_b,
                            const float* __restrict__ var_b,
                            float* __restrict__ mu_out) {
    int row  = (int)((blockIdx.x * blockDim.x + threadIdx.x) >> 5);
    int lane = threadIdx.x & 31;
    if (row >= NROWS) return;

    const float* xr = x + (size_t)row * DDIM;
    __nv_bfloat16* Xr = g_X + (size_t)row * KBIG;
    __nv_bfloat16* Yr = g_Y + (size_t)row * KBIG;

    float smu = 0.f, sv = 0.f;
#pragma unroll
    for (int k = lane; k < DDIM; k += 32) {
        float xv = xr[k];
        smu = fmaf(xv, mu_k[k], smu);
        sv  = fmaf(xv, var_k[k], sv);
        float yv = xv * rho[k];

        __nv_bfloat16 xh = __float2bfloat16(xv);
        __nv_bfloat16 xl = __float2bfloat16(xv - __bfloat162float(xh));
        __nv_bfloat16 yh = __float2bfloat16(yv);
        __nv_bfloat16 yl = __float2bfloat16(yv - __bfloat162float(yh));

        Xr[k] = xh; Xr[DDIM + k] = xl; Xr[2 * DDIM + k] = xh;
        Yr[k] = yh; Yr[DDIM + k] = yh; Yr[2 * DDIM + k] = yl;
    }
#pragma unroll
    for (int o = 16; o > 0; o >>= 1) {
        smu += __shfl_down_sync(0xffffffffu, smu, o);
        sv  += __shfl_down_sync(0xffffffffu, sv,  o);
    }
    if (lane == 0) {
        mu_out[row] = smu + mu_b[0];
        float z  = sv + var_b[0];
        float sp = (z > 20.f) ? z : log1pf(expf(z));
        g_d[row] = sp + 1e-8f;
    }
}

// ---------------------------------------------------------------------------
// Kernel 2: bf16 HMMA GEMM, block tile 128x256, warp tile 64x64 (8 warps),
// K=1536, 3-stage cp.async pipeline, triangular grid (r <= 2c+1).
// Diagonal-straddling tiles skip the mirror (primary writes cover it),
// so every output element has exactly one writer (deterministic).
// ---------------------------------------------------------------------------
__global__ __launch_bounds__(256, 1)
void cov_gemm_mma(float* __restrict__ C, const float* __restrict__ cov_b) {
    extern __shared__ char smem[];
    const uint32_t sb = smem_u32(smem);
    const int tid  = threadIdx.x;
    const int wid  = tid >> 5;
    const int lane = tid & 31;
    const int wm   = wid & 1;    // m offset wm*64
    const int wn   = wid >> 1;   // n offset wn*64

    // blockIdx -> (r, c): b = c(c+1) + r, r in [0, 2c+2)
    int b = blockIdx.x;
    int c = (int)((sqrtf(4.0f * (float)b + 1.0f) - 1.0f) * 0.5f);
    while ((c + 1) * (c + 2) <= b) c++;
    while (c * (c + 1) > b) c--;
    const int r  = b - c * (c + 1);
    const int i0 = r << 7;   // 128-row tile
    const int j0 = c << 8;   // 256-col tile

    const __nv_bfloat16* Ab = g_Y + (size_t)i0 * KBIG;
    const __nv_bfloat16* Bb = g_X + (size_t)j0 * KBIG;

    float acc[4][8][4];
#pragma unroll
    for (int mt = 0; mt < 4; mt++)
#pragma unroll
        for (int nt = 0; nt < 8; nt++)
#pragma unroll
            for (int q = 0; q < 4; q++) acc[mt][nt][q] = 0.f;

    // ---- stage loader: A 1024 vec16 + B 2048 vec16 = 12 per thread ----
    auto load_stage = [&](int s, int kt) {
        const int k0 = kt * BK;
        const uint32_t sA = sb + s * STAGE_BYTES;
        const uint32_t sB = sA + 16384;
#pragma unroll
        for (int v = 0; v < 12; v++) {
            int e = tid + v * 256;
            if (e < 1024) {
                int row = e >> 3, c16 = e & 7;
                cpa16(sA + SWZ(row * 128 + c16 * 16),
                      Ab + (size_t)row * KBIG + k0 + c16 * 8);
            } else {
                int eb = e - 1024;
                int row = eb >> 3, c16 = eb & 7;
                cpa16(sB + SWZ(row * 128 + c16 * 16),
                      Bb + (size_t)row * KBIG + k0 + c16 * 8);
            }
        }
    };

    // ---- prologue: 2 stages in flight ----
    load_stage(0, 0);
    asm volatile("cp.async.commit_group;" ::: "memory");
    load_stage(1, 1);
    asm volatile("cp.async.commit_group;" ::: "memory");

    // ldmatrix lane addressing
    const int a_row = lane & 15;
    const int a_kb  = (lane >> 4) * 16;
    const int b_g   = lane >> 3;
    const int b_r   = lane & 7;
    const int b_row = ((b_g >> 1) * 8) + b_r;
    const int b_kb  = (b_g & 1) * 16;

    // ---- main loop ----
    int scur = 0, sload = 2;
    for (int kt = 0; kt < NCHUNK; kt++) {
        asm volatile("cp.async.wait_group 1;" ::: "memory");
        __syncthreads();

        if (kt + 2 < NCHUNK) load_stage(sload, kt + 2);
        asm volatile("cp.async.commit_group;" ::: "memory");

        const uint32_t sA = sb + scur * STAGE_BYTES;
        const uint32_t sB = sA + 16384;

#pragma unroll
        for (int kk = 0; kk < 4; kk++) {
            uint32_t afr[4][4];
#pragma unroll
            for (int mt = 0; mt < 4; mt++) {
                int row = wm * 64 + mt * 16 + a_row;
                ldsm_x4(afr[mt], sA + SWZ(row * 128 + kk * 32 + a_kb));
            }
            uint32_t bfr[4][4];
#pragma unroll
            for (int q = 0; q < 4; q++) {
                int row = wn * 64 + q * 16 + b_row;
                ldsm_x4(bfr[q], sB + SWZ(row * 128 + kk * 32 + b_kb));
            }
#pragma unroll
            for (int mt = 0; mt < 4; mt++)
#pragma unroll
                for (int nt = 0; nt < 8; nt++) {
                    int q = nt >> 1, h = nt & 1;
                    mma16816(acc[mt][nt], afr[mt], bfr[q][2 * h], bfr[q][2 * h + 1]);
                }
        }
        scur = (scur == 2) ? 0 : scur + 1;
        sload = (sload == 2) ? 0 : sload + 1;
    }
    asm volatile("cp.async.wait_group 0;" ::: "memory");
    __syncthreads();   // pipeline drained; smem reusable for transpose

    // ---- epilogue ----
    const float cb = cov_b[0];
    const int g4 = lane >> 2;
    const int t2 = lane & 3;
    const bool straddle = ((r >> 1) == c);   // tile contains the diagonal band

    float* st = (float*)smem;   // 256 x TPITCH transpose buffer (j-major)

#pragma unroll
    for (int mt = 0; mt < 4; mt++)
#pragma unroll
        for (int nt = 0; nt < 8; nt++) {
            int il = wm * 64 + mt * 16 + g4;
            int jl = wn * 64 + nt * 8 + t2 * 2;
            float v0 = acc[mt][nt][0] + cb;
            float v1 = acc[mt][nt][1] + cb;
            float v2 = acc[mt][nt][2] + cb;
            float v3 = acc[mt][nt][3] + cb;

            size_t o0 = (size_t)(i0 + il) * NROWS + (j0 + jl);
            size_t o1 = (size_t)(i0 + il + 8) * NROWS + (j0 + jl);
            *(float2*)(C + o0) = make_float2(v0, v1);
            *(float2*)(C + o1) = make_float2(v2, v3);

            if (!straddle) {
                st[(jl + 0) * TPITCH + il]     = v0;
                st[(jl + 1) * TPITCH + il]     = v1;
                st[(jl + 0) * TPITCH + il + 8] = v2;
                st[(jl + 1) * TPITCH + il + 8] = v3;
            }
        }

    if (!straddle) {   // mirror 256x128 transposed block into the lower triangle
        __syncthreads();
#pragma unroll
        for (int it = 0; it < 32; it++) {
            int jj = it * 8 + wid;
            float4 v = *(float4*)(st + jj * TPITCH + lane * 4);
            *(float4*)(C + (size_t)(j0 + jj) * NROWS + i0 + lane * 4) = v;
        }
    }
}

// ---------------------------------------------------------------------------
// Kernel 3: diagonal overwrite.
// ---------------------------------------------------------------------------
__global__ void set_diag(float* __restrict__ C) {
    int i = blockIdx.x * blockDim.x + threadIdx.x;
    if (i < NROWS) C[(size_t)i * NROWS + i] = g_d[i];
}

// ---------------------------------------------------------------------------
extern "C" void kernel_launch(void* const* d_in, const int* in_sizes, int n_in,
                              void* d_out, int out_size) {
    (void)in_sizes; (void)n_in; (void)out_size;
    const float* x     = (const float*)d_in[0];
    const float* mu_k  = (const float*)d_in[1];
    const float* rho   = (const float*)d_in[2];
    const float* var_k = (const float*)d_in[3];
    const float* mu_b  = (const float*)d_in[4];
    const float* var_b = (const float*)d_in[5];
    const float* cov_b = (const float*)d_in[6];

    float* out = (float*)d_out;
    float* mu  = out;
    float* cov = out + NROWS;

    cudaFuncSetAttribute(cov_gemm_mma, cudaFuncAttributeMaxDynamicSharedMemorySize, SMEM_TOTAL);

    prep_kernel<<<NROWS / 8, 256>>>(x, mu_k, rho, var_k, mu_b, var_b, mu);

    // 1056 = sum_{c=0}^{31} (2c+2) upper-cover 128x256 tiles
    cov_gemm_mma<<<1056, 256, SMEM_TOTAL>>>(cov, cov_b);

    set_diag<<<NROWS / 256, 256>>>(cov);
}

// round 13
// speedup vs baseline: 2.7256x; 1.0006x over previous
#include <cuda_runtime.h>
#include <cuda_bf16.h>
#include <cstdint>

// Problem constants: N=8192, D=512, OUT=1
#define NROWS 8192
#define DDIM  512
#define KBIG  1536            // split-bf16 concatenated K: [hi | cross | cross]
#define BK    64              // bf16 per K-chunk = 128 bytes/row
#define NCHUNK (KBIG / BK)    // 24
#define NSTAGE 3
#define STAGE_BYTES 49152     // A 128x64x2 = 16KB + B 256x64x2 = 32KB
#define SMEM_TOTAL (NSTAGE * STAGE_BYTES)   // 147456
#define TPITCH 132            // fp32 pitch for epilogue transpose buffer

// Scratch in __device__ globals (no allocations allowed)
__device__ __nv_bfloat16 g_X[(size_t)NROWS * KBIG];  // [xh | xl | xh]
__device__ __nv_bfloat16 g_Y[(size_t)NROWS * KBIG];  // [yh | yh | yl]
__device__ float g_d[NROWS];

// ---------------- helpers ----------------
__device__ __forceinline__ uint32_t smem_u32(const void* p) {
    uint32_t a;
    asm("{ .reg .u64 t; cvta.to.shared.u64 t, %1; cvt.u32.u64 %0, t; }" : "=r"(a) : "l"(p));
    return a;
}
__device__ __forceinline__ void cpa16(uint32_t s, const void* g) {
    asm volatile("cp.async.cg.shared.global [%0], [%1], 16;"
                 :: "r"(s), "l"(__cvta_generic_to_global(g)) : "memory");
}
#define SWZ(o) ((o) ^ (((o) >> 3) & 0x70))

__device__ __forceinline__ void ldsm_x4(uint32_t* r, uint32_t addr) {
    asm volatile("ldmatrix.sync.aligned.m8n8.x4.shared.b16 {%0,%1,%2,%3}, [%4];"
                 : "=r"(r[0]), "=r"(r[1]), "=r"(r[2]), "=r"(r[3]) : "r"(addr));
}
__device__ __forceinline__ void mma16816(float* c, const uint32_t* a, uint32_t b0, uint32_t b1) {
    asm volatile("mma.sync.aligned.m16n8k16.row.col.f32.bf16.bf16.f32 "
                 "{%0,%1,%2,%3}, {%4,%5,%6,%7}, {%8,%9}, {%0,%1,%2,%3};"
                 : "+f"(c[0]), "+f"(c[1]), "+f"(c[2]), "+f"(c[3])
                 : "r"(a[0]), "r"(a[1]), "r"(a[2]), "r"(a[3]), "r"(b0), "r"(b1));
}

// ---------------------------------------------------------------------------
// Kernel 1: one warp per row — mu, softplus d, split-bf16 operand build.
// ---------------------------------------------------------------------------
__global__ void prep_kernel(const float* __restrict__ x,
                            const float* __restrict__ mu_k,
                            const float* __restrict__ rho,
                            const float* __restrict__ var_k,
                            const float* __restrict__ mu_b,
                            const float* __restrict__ var_b,
                            float* __restrict__ mu_out) {
    int row  = (int)((blockIdx.x * blockDim.x + threadIdx.x) >> 5);
    int lane = threadIdx.x & 31;
    if (row >= NROWS) return;

    const float* xr = x + (size_t)row * DDIM;
    __nv_bfloat16* Xr = g_X + (size_t)row * KBIG;
    __nv_bfloat16* Yr = g_Y + (size_t)row * KBIG;

    float smu = 0.f, sv = 0.f;
#pragma unroll
    for (int k = lane; k < DDIM; k += 32) {
        float xv = xr[k];
        smu = fmaf(xv, mu_k[k], smu);
        sv  = fmaf(xv, var_k[k], sv);
        float yv = xv * rho[k];

        __nv_bfloat16 xh = __float2bfloat16(xv);
        __nv_bfloat16 xl = __float2bfloat16(xv - __bfloat162float(xh));
        __nv_bfloat16 yh = __float2bfloat16(yv);
        __nv_bfloat16 yl = __float2bfloat16(yv - __bfloat162float(yh));

        Xr[k] = xh; Xr[DDIM + k] = xl; Xr[2 * DDIM + k] = xh;
        Yr[k] = yh; Yr[DDIM + k] = yh; Yr[2 * DDIM + k] = yl;
    }
#pragma unroll
    for (int o = 16; o > 0; o >>= 1) {
        smu += __shfl_down_sync(0xffffffffu, smu, o);
        sv  += __shfl_down_sync(0xffffffffu, sv,  o);
    }
    if (lane == 0) {
        mu_out[row] = smu + mu_b[0];
        float z  = sv + var_b[0];
        float sp = (z > 20.f) ? z : log1pf(expf(z));
        g_d[row] = sp + 1e-8f;
    }
}

// ---------------------------------------------------------------------------
// Kernel 2: bf16 HMMA GEMM, block tile 128x256, warp tile 64x64 (8 warps),
// K=1536, 3-stage cp.async pipeline, triangular grid (r <= 2c+1).
// Diagonal-straddling tiles skip the mirror (primary writes cover it),
// so every output element has exactly one writer (deterministic).
// ---------------------------------------------------------------------------
__global__ __launch_bounds__(256, 1)
void cov_gemm_mma(float* __restrict__ C, const float* __restrict__ cov_b) {
    extern __shared__ char smem[];
    const uint32_t sb = smem_u32(smem);
    const int tid  = threadIdx.x;
    const int wid  = tid >> 5;
    const int lane = tid & 31;
    const int wm   = wid & 1;    // m offset wm*64
    const int wn   = wid >> 1;   // n offset wn*64

    // blockIdx -> (r, c): b = c(c+1) + r, r in [0, 2c+2)
    int b = blockIdx.x;
    int c = (int)((sqrtf(4.0f * (float)b + 1.0f) - 1.0f) * 0.5f);
    while ((c + 1) * (c + 2) <= b) c++;
    while (c * (c + 1) > b) c--;
    const int r  = b - c * (c + 1);
    const int i0 = r << 7;   // 128-row tile
    const int j0 = c << 8;   // 256-col tile

    const __nv_bfloat16* Ab = g_Y + (size_t)i0 * KBIG;
    const __nv_bfloat16* Bb = g_X + (size_t)j0 * KBIG;

    float acc[4][8][4];
#pragma unroll
    for (int mt = 0; mt < 4; mt++)
#pragma unroll
        for (int nt = 0; nt < 8; nt++)
#pragma unroll
            for (int q = 0; q < 4; q++) acc[mt][nt][q] = 0.f;

    // ---- stage loader: A 1024 vec16 + B 2048 vec16 = 12 per thread ----
    auto load_stage = [&](int s, int kt) {
        const int k0 = kt * BK;
        const uint32_t sA = sb + s * STAGE_BYTES;
        const uint32_t sB = sA + 16384;
#pragma unroll
        for (int v = 0; v < 12; v++) {
            int e = tid + v * 256;
            if (e < 1024) {
                int row = e >> 3, c16 = e & 7;
                cpa16(sA + SWZ(row * 128 + c16 * 16),
                      Ab + (size_t)row * KBIG + k0 + c16 * 8);
            } else {
                int eb = e - 1024;
                int row = eb >> 3, c16 = eb & 7;
                cpa16(sB + SWZ(row * 128 + c16 * 16),
                      Bb + (size_t)row * KBIG + k0 + c16 * 8);
            }
        }
    };

    // ---- prologue: 2 stages in flight ----
    load_stage(0, 0);
    asm volatile("cp.async.commit_group;" ::: "memory");
    load_stage(1, 1);
    asm volatile("cp.async.commit_group;" ::: "memory");

    // ldmatrix lane addressing
    const int a_row = lane & 15;
    const int a_kb  = (lane >> 4) * 16;
    const int b_g   = lane >> 3;
    const int b_r   = lane & 7;
    const int b_row = ((b_g >> 1) * 8) + b_r;
    const int b_kb  = (b_g & 1) * 16;

    // ---- main loop ----
    int scur = 0, sload = 2;
    for (int kt = 0; kt < NCHUNK; kt++) {
        asm volatile("cp.async.wait_group 1;" ::: "memory");
        __syncthreads();

        if (kt + 2 < NCHUNK) load_stage(sload, kt + 2);
        asm volatile("cp.async.commit_group;" ::: "memory");

        const uint32_t sA = sb + scur * STAGE_BYTES;
        const uint32_t sB = sA + 16384;

#pragma unroll
        for (int kk = 0; kk < 4; kk++) {
            uint32_t afr[4][4];
#pragma unroll
            for (int mt = 0; mt < 4; mt++) {
                int row = wm * 64 + mt * 16 + a_row;
                ldsm_x4(afr[mt], sA + SWZ(row * 128 + kk * 32 + a_kb));
            }
            uint32_t bfr[4][4];
#pragma unroll
            for (int q = 0; q < 4; q++) {
                int row = wn * 64 + q * 16 + b_row;
                ldsm_x4(bfr[q], sB + SWZ(row * 128 + kk * 32 + b_kb));
            }
#pragma unroll
            for (int mt = 0; mt < 4; mt++)
#pragma unroll
                for (int nt = 0; nt < 8; nt++) {
                    int q = nt >> 1, h = nt & 1;
                    mma16816(acc[mt][nt], afr[mt], bfr[q][2 * h], bfr[q][2 * h + 1]);
                }
        }
        scur = (scur == 2) ? 0 : scur + 1;
        sload = (sload == 2) ? 0 : sload + 1;
    }
    asm volatile("cp.async.wait_group 0;" ::: "memory");
    __syncthreads();   // pipeline drained; smem reusable for transpose

    // ---- epilogue ----
    const float cb = cov_b[0];
    const int g4 = lane >> 2;
    const int t2 = lane & 3;
    const bool straddle = ((r >> 1) == c);   // tile contains the diagonal band

    float* st = (float*)smem;   // 256 x TPITCH transpose buffer (j-major)

#pragma unroll
    for (int mt = 0; mt < 4; mt++)
#pragma unroll
        for (int nt = 0; nt < 8; nt++) {
            int il = wm * 64 + mt * 16 + g4;
            int jl = wn * 64 + nt * 8 + t2 * 2;
            float v0 = acc[mt][nt][0] + cb;
            float v1 = acc[mt][nt][1] + cb;
            float v2 = acc[mt][nt][2] + cb;
            float v3 = acc[mt][nt][3] + cb;

            size_t o0 = (size_t)(i0 + il) * NROWS + (j0 + jl);
            size_t o1 = (size_t)(i0 + il + 8) * NROWS + (j0 + jl);
            *(float2*)(C + o0) = make_float2(v0, v1);
            *(float2*)(C + o1) = make_float2(v2, v3);

            if (!straddle) {
                st[(jl + 0) * TPITCH + il]     = v0;
                st[(jl + 1) * TPITCH + il]     = v1;
                st[(jl + 0) * TPITCH + il + 8] = v2;
                st[(jl + 1) * TPITCH + il + 8] = v3;
            }
        }

    if (!straddle) {   // mirror 256x128 transposed block into the lower triangle
        __syncthreads();
#pragma unroll
        for (int it = 0; it < 32; it++) {
            int jj = it * 8 + wid;
            float4 v = *(float4*)(st + jj * TPITCH + lane * 4);
            *(float4*)(C + (size_t)(j0 + jj) * NROWS + i0 + lane * 4) = v;
        }
    }
}

// ---------------------------------------------------------------------------
// Kernel 3: diagonal overwrite.
// ---------------------------------------------------------------------------
__global__ void set_diag(float* __restrict__ C) {
    int i = blockIdx.x * blockDim.x + threadIdx.x;
    if (i < NROWS) C[(size_t)i * NROWS + i] = g_d[i];
}

// ---------------------------------------------------------------------------
extern "C" void kernel_launch(void* const* d_in, const int* in_sizes, int n_in,
                              void* d_out, int out_size) {
    (void)in_sizes; (void)n_in; (void)out_size;
    const float* x     = (const float*)d_in[0];
    const float* mu_k  = (const float*)d_in[1];
    const float* rho   = (const float*)d_in[2];
    const float* var_k = (const float*)d_in[3];
    const float* mu_b  = (const float*)d_in[4];
    const float* var_b = (const float*)d_in[5];
    const float* cov_b = (const float*)d_in[6];

    float* out = (float*)d_out;
    float* mu  = out;
    float* cov = out + NROWS;

    cudaFuncSetAttribute(cov_gemm_mma, cudaFuncAttributeMaxDynamicSharedMemorySize, SMEM_TOTAL);

    prep_kernel<<<NROWS / 8, 256>>>(x, mu_k, rho, var_k, mu_b, var_b, mu);

    // 1056 = sum_{c=0}^{31} (2c+2) upper-cover 128x256 tiles
    cov_gemm_mma<<<1056, 256, SMEM_TOTAL>>>(cov, cov_b);

    set_diag<<<NROWS / 256, 256>>>(cov);
}

// round 14
// speedup vs baseline: 3.7025x; 1.3584x over previous
#include <cuda_runtime.h>
#include <cuda_fp16.h>
#include <cstdint>

// Problem constants: N=8192, D=512, OUT=1
#define NROWS 8192
#define DDIM  512
#define KBIG  1024            // split-fp16 concatenated K: [hi | residual]
#define BK    64              // fp16 per K-chunk = 128 bytes/row
#define NCHUNK (KBIG / BK)    // 16
#define NSTAGE 3
#define STAGE_BYTES 49152     // A 128x64x2 = 16KB + B 256x64x2 = 32KB
#define SMEM_TOTAL (NSTAGE * STAGE_BYTES)   // 147456
#define TPITCH 132            // fp32 pitch for epilogue transpose buffer

// Scratch in __device__ globals (no allocations allowed)
__device__ __half g_X[(size_t)NROWS * KBIG];  // [xh | xl]   (xl = fp16(x - xh))
__device__ __half g_Y[(size_t)NROWS * KBIG];  // [yh | yh]   (y = x * rho)
__device__ float g_d[NROWS];

// ---------------- helpers ----------------
__device__ __forceinline__ uint32_t smem_u32(const void* p) {
    uint32_t a;
    asm("{ .reg .u64 t; cvta.to.shared.u64 t, %1; cvt.u32.u64 %0, t; }" : "=r"(a) : "l"(p));
    return a;
}
__device__ __forceinline__ void cpa16(uint32_t s, const void* g) {
    asm volatile("cp.async.cg.shared.global [%0], [%1], 16;"
                 :: "r"(s), "l"(__cvta_generic_to_global(g)) : "memory");
}
#define SWZ(o) ((o) ^ (((o) >> 3) & 0x70))

__device__ __forceinline__ void ldsm_x4(uint32_t* r, uint32_t addr) {
    asm volatile("ldmatrix.sync.aligned.m8n8.x4.shared.b16 {%0,%1,%2,%3}, [%4];"
                 : "=r"(r[0]), "=r"(r[1]), "=r"(r[2]), "=r"(r[3]) : "r"(addr));
}
__device__ __forceinline__ void mma16816(float* c, const uint32_t* a, uint32_t b0, uint32_t b1) {
    asm volatile("mma.sync.aligned.m16n8k16.row.col.f32.f16.f16.f32 "
                 "{%0,%1,%2,%3}, {%4,%5,%6,%7}, {%8,%9}, {%0,%1,%2,%3};"
                 : "+f"(c[0]), "+f"(c[1]), "+f"(c[2]), "+f"(c[3])
                 : "r"(a[0]), "r"(a[1]), "r"(a[2]), "r"(a[3]), "r"(b0), "r"(b1));
}

// ---------------------------------------------------------------------------
// Kernel 1: one warp per row — mu, softplus d, split-fp16 operand build.
//   g_Y[i] = [yh | yh],  g_X[i] = [xh | xl],  y = x * rho
// ---------------------------------------------------------------------------
__global__ void prep_kernel(const float* __restrict__ x,
                            const float* __restrict__ mu_k,
                            const float* __restrict__ rho,
                            const float* __restrict__ var_k,
                            const float* __restrict__ mu_b,
                            const float* __restrict__ var_b,
                            float* __restrict__ mu_out) {
    int row  = (int)((blockIdx.x * blockDim.x + threadIdx.x) >> 5);
    int lane = threadIdx.x & 31;
    if (row >= NROWS) return;

    const float* xr = x + (size_t)row * DDIM;
    __half* Xr = g_X + (size_t)row * KBIG;
    __half* Yr = g_Y + (size_t)row * KBIG;

    float smu = 0.f, sv = 0.f;
#pragma unroll
    for (int k = lane; k < DDIM; k += 32) {
        float xv = xr[k];
        smu = fmaf(xv, mu_k[k], smu);
        sv  = fmaf(xv, var_k[k], sv);
        float yv = xv * rho[k];

        __half xh = __float2half_rn(xv);
        __half xl = __float2half_rn(xv - __half2float(xh));
        __half yh = __float2half_rn(yv);

        Xr[k] = xh; Xr[DDIM + k] = xl;
        Yr[k] = yh; Yr[DDIM + k] = yh;
    }
#pragma unroll
    for (int o = 16; o > 0; o >>= 1) {
        smu += __shfl_down_sync(0xffffffffu, smu, o);
        sv  += __shfl_down_sync(0xffffffffu, sv,  o);
    }
    if (lane == 0) {
        mu_out[row] = smu + mu_b[0];
        float z  = sv + var_b[0];
        float sp = (z > 20.f) ? z : log1pf(expf(z));
        g_d[row] = sp + 1e-8f;
    }
}

// ---------------------------------------------------------------------------
// Kernel 2: fp16 HMMA GEMM, block tile 128x256, warp tile 64x64 (8 warps),
// K=1024, 3-stage cp.async pipeline, triangular grid (r <= 2c+1).
// Diagonal-straddling tiles skip the mirror (primary writes cover it),
// so every output element has exactly one writer (deterministic).
// ---------------------------------------------------------------------------
__global__ __launch_bounds__(256, 1)
void cov_gemm_mma(float* __restrict__ C, const float* __restrict__ cov_b) {
    extern __shared__ char smem[];
    const uint32_t sb = smem_u32(smem);
    const int tid  = threadIdx.x;
    const int wid  = tid >> 5;
    const int lane = tid & 31;
    const int wm   = wid & 1;    // m offset wm*64
    const int wn   = wid >> 1;   // n offset wn*64

    // blockIdx -> (r, c): b = c(c+1) + r, r in [0, 2c+2)
    int b = blockIdx.x;
    int c = (int)((sqrtf(4.0f * (float)b + 1.0f) - 1.0f) * 0.5f);
    while ((c + 1) * (c + 2) <= b) c++;
    while (c * (c + 1) > b) c--;
    const int r  = b - c * (c + 1);
    const int i0 = r << 7;   // 128-row tile
    const int j0 = c << 8;   // 256-col tile

    const __half* Ab = g_Y + (size_t)i0 * KBIG;
    const __half* Bb = g_X + (size_t)j0 * KBIG;

    float acc[4][8][4];
#pragma unroll
    for (int mt = 0; mt < 4; mt++)
#pragma unroll
        for (int nt = 0; nt < 8; nt++)
#pragma unroll
            for (int q = 0; q < 4; q++) acc[mt][nt][q] = 0.f;

    // ---- stage loader: A 1024 vec16 + B 2048 vec16 = 12 per thread ----
    auto load_stage = [&](int s, int kt) {
        const int k0 = kt * BK;
        const uint32_t sA = sb + s * STAGE_BYTES;
        const uint32_t sB = sA + 16384;
#pragma unroll
        for (int v = 0; v < 12; v++) {
            int e = tid + v * 256;
            if (e < 1024) {
                int row = e >> 3, c16 = e & 7;
                cpa16(sA + SWZ(row * 128 + c16 * 16),
                      Ab + (size_t)row * KBIG + k0 + c16 * 8);
            } else {
                int eb = e - 1024;
                int row = eb >> 3, c16 = eb & 7;
                cpa16(sB + SWZ(row * 128 + c16 * 16),
                      Bb + (size_t)row * KBIG + k0 + c16 * 8);
            }
        }
    };

    // ---- prologue: 2 stages in flight ----
    load_stage(0, 0);
    asm volatile("cp.async.commit_group;" ::: "memory");
    load_stage(1, 1);
    asm volatile("cp.async.commit_group;" ::: "memory");

    // ldmatrix lane addressing
    const int a_row = lane & 15;
    const int a_kb  = (lane >> 4) * 16;
    const int b_g   = lane >> 3;
    const int b_r   = lane & 7;
    const int b_row = ((b_g >> 1) * 8) + b_r;
    const int b_kb  = (b_g & 1) * 16;

    // ---- main loop ----
    int scur = 0, sload = 2;
    for (int kt = 0; kt < NCHUNK; kt++) {
        asm volatile("cp.async.wait_group 1;" ::: "memory");
        __syncthreads();

        if (kt + 2 < NCHUNK) load_stage(sload, kt + 2);
        asm volatile("cp.async.commit_group;" ::: "memory");

        const uint32_t sA = sb + scur * STAGE_BYTES;
        const uint32_t sB = sA + 16384;

#pragma unroll
        for (int kk = 0; kk < 4; kk++) {
            uint32_t afr[4][4];
#pragma unroll
            for (int mt = 0; mt < 4; mt++) {
                int row = wm * 64 + mt * 16 + a_row;
                ldsm_x4(afr[mt], sA + SWZ(row * 128 + kk * 32 + a_kb));
            }
            uint32_t bfr[4][4];
#pragma unroll
            for (int q = 0; q < 4; q++) {
                int row = wn * 64 + q * 16 + b_row;
                ldsm_x4(bfr[q], sB + SWZ(row * 128 + kk * 32 + b_kb));
            }
#pragma unroll
            for (int mt = 0; mt < 4; mt++)
#pragma unroll
                for (int nt = 0; nt < 8; nt++) {
                    int q = nt >> 1, h = nt & 1;
                    mma16816(acc[mt][nt], afr[mt], bfr[q][2 * h], bfr[q][2 * h + 1]);
                }
        }
        scur = (scur == 2) ? 0 : scur + 1;
        sload = (sload == 2) ? 0 : sload + 1;
    }
    asm volatile("cp.async.wait_group 0;" ::: "memory");
    __syncthreads();   // pipeline drained; smem reusable for transpose

    // ---- epilogue ----
    const float cb = cov_b[0];
    const int g4 = lane >> 2;
    const int t2 = lane & 3;
    const bool straddle = ((r >> 1) == c);   // tile contains the diagonal band

    float* st = (float*)smem;   // 256 x TPITCH transpose buffer (j-major)

#pragma unroll
    for (int mt = 0; mt < 4; mt++)
#pragma unroll
        for (int nt = 0; nt < 8; nt++) {
            int il = wm * 64 + mt * 16 + g4;
            int jl = wn * 64 + nt * 8 + t2 * 2;
            float v0 = acc[mt][nt][0] + cb;
            float v1 = acc[mt][nt][1] + cb;
            float v2 = acc[mt][nt][2] + cb;
            float v3 = acc[mt][nt][3] + cb;

            size_t o0 = (size_t)(i0 + il) * NROWS + (j0 + jl);
            size_t o1 = (size_t)(i0 + il + 8) * NROWS + (j0 + jl);
            *(float2*)(C + o0) = make_float2(v0, v1);
            *(float2*)(C + o1) = make_float2(v2, v3);

            if (!straddle) {
                st[(jl + 0) * TPITCH + il]     = v0;
                st[(jl + 1) * TPITCH + il]     = v1;
                st[(jl + 0) * TPITCH + il + 8] = v2;
                st[(jl + 1) * TPITCH + il + 8] = v3;
            }
        }

    if (!straddle) {   // mirror 256x128 transposed block into the lower triangle
        __syncthreads();
#pragma unroll
        for (int it = 0; it < 32; it++) {
            int jj = it * 8 + wid;
            float4 v = *(float4*)(st + jj * TPITCH + lane * 4);
            *(float4*)(C + (size_t)(j0 + jj) * NROWS + i0 + lane * 4) = v;
        }
    }
}

// ---------------------------------------------------------------------------
// Kernel 3: diagonal overwrite.
// ---------------------------------------------------------------------------
__global__ void set_diag(float* __restrict__ C) {
    int i = blockIdx.x * blockDim.x + threadIdx.x;
    if (i < NROWS) C[(size_t)i * NROWS + i] = g_d[i];
}

// ---------------------------------------------------------------------------
extern "C" void kernel_launch(void* const* d_in, const int* in_sizes, int n_in,
                              void* d_out, int out_size) {
    (void)in_sizes; (void)n_in; (void)out_size;
    const float* x     = (const float*)d_in[0];
    const float* mu_k  = (const float*)d_in[1];
    const float* rho   = (const float*)d_in[2];
    const float* var_k = (const float*)d_in[3];
    const float* mu_b  = (const float*)d_in[4];
    const float* var_b = (const float*)d_in[5];
    const float* cov_b = (const float*)d_in[6];

    float* out = (float*)d_out;
    float* mu  = out;
    float* cov = out + NROWS;

    cudaFuncSetAttribute(cov_gemm_mma, cudaFuncAttributeMaxDynamicSharedMemorySize, SMEM_TOTAL);

    prep_kernel<<<NROWS / 8, 256>>>(x, mu_k, rho, var_k, mu_b, var_b, mu);

    // 1056 = sum_{c=0}^{31} (2c+2) upper-cover 128x256 tiles
    cov_gemm_mma<<<1056, 256, SMEM_TOTAL>>>(cov, cov_b);

    set_diag<<<NROWS / 256, 256>>>(cov);
}